// round 2
// baseline (speedup 1.0000x reference)
#include <cuda_runtime.h>
#include <math.h>

#define N_NODES 8000
#define FDIM    128
#define EDGES   256000
#define C0      400
#define C1      20

// ---------------- static device scratch (no runtime allocation) ----------------
__device__ float g_xbn[N_NODES*FDIM];
__device__ float g_xp0[N_NODES*FDIM];
__device__ float g_xp1[N_NODES*FDIM];
__device__ float g_h  [N_NODES*FDIM];
__device__ float g_h2 [N_NODES*FDIM];
__device__ float g_S0 [N_NODES*C0];
__device__ float g_corr0[N_NODES*FDIM];
__device__ float g_colsum0[C0];
__device__ float g_colsum1[C1];
__device__ float g_xc1  [C0*FDIM];
__device__ float g_corr1[C0*FDIM];
__device__ float g_T0   [C0*FDIM];
__device__ float g_G0   [C0*FDIM];
__device__ float g_S1   [C0*C1];
__device__ float g_xc2  [C1*FDIM];
__device__ float g_corr2[C1*FDIM];
__device__ float g_T1   [C1*FDIM];
__device__ float g_G1   [C1*FDIM];
__device__ float g_P1   [N_NODES*C1];
__device__ float g_csA  [C0];
__device__ float g_cssA [C0];
__device__ int   g_cnt[N_NODES];
__device__ int   g_off[N_NODES+1];
__device__ int   g_cur[N_NODES];
__device__ int   g_colS[EDGES];
__device__ float g_wS  [EDGES];
__device__ float g_mA[(size_t)FDIM*EDGES];   // f-major [F][E], k=20 mask
__device__ float g_mB[(size_t)FDIM*EDGES];   // f-major [F][E], k=400 mask

// ---------------- column reductions (atomic partials) ----------------
__global__ void k_colsum(const float* __restrict__ A, int n, int c, int rowsPer,
                         float* __restrict__ out) {
    int r0 = blockIdx.x * rowsPer;
    int r1 = min(n, r0 + rowsPer);
    for (int col = threadIdx.x; col < c; col += blockDim.x) {
        float s = 0.f;
        for (int r = r0; r < r1; r++) s += A[(size_t)r * c + col];
        atomicAdd(&out[col], s);
    }
}

__global__ void k_colcss(const float* __restrict__ A, int n, int c, int rowsPer,
                         const float* __restrict__ colsum, float* __restrict__ out) {
    int r0 = blockIdx.x * rowsPer;
    int r1 = min(n, r0 + rowsPer);
    for (int col = threadIdx.x; col < c; col += blockDim.x) {
        float m = colsum[col] / (float)n;
        float s = 0.f;
        for (int r = r0; r < r1; r++) {
            float d = A[(size_t)r * c + col] - m;
            s += d * d;
        }
        atomicAdd(&out[col], s);
    }
}

// ---------------- batchnorm apply ----------------
__global__ void k_bn(const float* __restrict__ x, const float* __restrict__ cs,
                     const float* __restrict__ css, const float* __restrict__ gam,
                     const float* __restrict__ bet, float* __restrict__ o) {
    int i = blockIdx.x * blockDim.x + threadIdx.x;
    if (i >= N_NODES * FDIM) return;
    int f = i & (FDIM - 1);
    float mu  = cs[f]  * (1.f / N_NODES);
    float var = css[f] * (1.f / N_NODES);
    o[i] = (x[i] - mu) * rsqrtf(var + 1e-5f) * gam[f] + bet[f];
}

// ---------------- node correlation: out[n,f] = zc_n[f] * sum_f' zc_n[f'] ----------------
__global__ void k_corr(const float* __restrict__ z, int n,
                       const float* __restrict__ cs, const float* __restrict__ css,
                       float* __restrict__ out) {
    int r = blockIdx.x, f = threadIdx.x;   // 128 threads
    float mean = cs[f] / (float)n;
    float inv  = 1.f / (sqrtf(css[f]) + 1e-12f);
    float v = (z[(size_t)r * FDIM + f] - mean) * inv;
    __shared__ float red[128];
    red[f] = v; __syncthreads();
    for (int s = 64; s > 0; s >>= 1) {
        if (f < s) red[f] += red[f + s];
        __syncthreads();
    }
    out[(size_t)r * FDIM + f] = v * red[0];
}

// ---------------- row softmax (in place) ----------------
__global__ void k_softmax(float* __restrict__ X, int W) {
    int r = blockIdx.x;
    float* row = X + (size_t)r * W;
    int t = threadIdx.x, bd = blockDim.x;
    __shared__ float red[128];
    float m = -3.4e38f;
    for (int c = t; c < W; c += bd) m = fmaxf(m, row[c]);
    red[t] = m; __syncthreads();
    for (int s = bd >> 1; s > 0; s >>= 1) {
        if (t < s) red[t] = fmaxf(red[t], red[t + s]);
        __syncthreads();
    }
    m = red[0]; __syncthreads();
    float sum = 0.f;
    for (int c = t; c < W; c += bd) { float e = expf(row[c] - m); row[c] = e; sum += e; }
    red[t] = sum; __syncthreads();
    for (int s = bd >> 1; s > 0; s >>= 1) {
        if (t < s) red[t] += red[t + s];
        __syncthreads();
    }
    float inv = 1.f / red[0];
    for (int c = t; c < W; c += bd) row[c] *= inv;
}

// ---------------- gains: g = sigmoid(c - t); store g*g ----------------
__global__ void k_gains(const float* __restrict__ c, const float* __restrict__ t,
                        float* __restrict__ g, int n) {
    int i = blockIdx.x * blockDim.x + threadIdx.x;
    if (i < n) {
        float x = 1.f / (1.f + expf(t[i] - c[i]));
        g[i] = x * x;
    }
}

// ---------------- generic tiled GEMM: C = act(A@B + bias) ----------------
// A [M,K] rm, B [K,N] rm. K % 16 == 0. act: 0 none, 1 relu, 2 prelu(aux[0]).
__global__ void k_gemm_nn(int M, int N, int K,
                          const float* __restrict__ A, const float* __restrict__ B,
                          const float* __restrict__ bias, float* __restrict__ C,
                          int act, const float* __restrict__ aux) {
    __shared__ __align__(16) float As[16][68];
    __shared__ __align__(16) float Bs[16][64];
    int t = threadIdx.x;
    int m0 = blockIdx.x * 64, n0 = blockIdx.y * 64;
    int tx = t & 15, ty = t >> 4;
    float acc[4][4];
#pragma unroll
    for (int i = 0; i < 4; i++)
#pragma unroll
        for (int j = 0; j < 4; j++) acc[i][j] = 0.f;
    for (int k0 = 0; k0 < K; k0 += 16) {
        __syncthreads();
        for (int idx = t; idx < 1024; idx += 256) {
            int kk = idx & 15, r = idx >> 4;
            int row = m0 + r;
            As[kk][r] = (row < M) ? A[(size_t)row * K + k0 + kk] : 0.f;
        }
        for (int idx = t; idx < 1024; idx += 256) {
            int kk = idx >> 6, c = idx & 63;
            int col = n0 + c;
            Bs[kk][c] = (col < N) ? B[(size_t)(k0 + kk) * N + col] : 0.f;
        }
        __syncthreads();
#pragma unroll
        for (int kk = 0; kk < 16; kk++) {
            float4 av = *(const float4*)&As[kk][ty * 4];
            float4 bv = *(const float4*)&Bs[kk][tx * 4];
            float a4[4] = {av.x, av.y, av.z, av.w};
            float b4[4] = {bv.x, bv.y, bv.z, bv.w};
#pragma unroll
            for (int i = 0; i < 4; i++)
#pragma unroll
                for (int j = 0; j < 4; j++) acc[i][j] += a4[i] * b4[j];
        }
    }
    float slope = (act == 2) ? aux[0] : 0.f;
#pragma unroll
    for (int i = 0; i < 4; i++) {
        int row = m0 + ty * 4 + i;
        if (row >= M) continue;
#pragma unroll
        for (int j = 0; j < 4; j++) {
            int col = n0 + tx * 4 + j;
            if (col >= N) continue;
            float v = acc[i][j];
            if (bias) v += bias[col];
            if (act == 1) v = fmaxf(v, 0.f);
            else if (act == 2) v = (v >= 0.f) ? v : slope * v;
            C[(size_t)row * N + col] = v;
        }
    }
}

// ---------------- GEMM C = A^T @ B, optional per-row divide ----------------
// A [Mr,K1] rm, B [Mr,N] rm, C [K1,N]. Mr % 16 == 0.
__global__ void k_gemm_tn(int Mr, int K1, int N,
                          const float* __restrict__ A, const float* __restrict__ B,
                          float* __restrict__ C, const float* __restrict__ divrow) {
    __shared__ __align__(16) float As[16][64];
    __shared__ __align__(16) float Bs[16][64];
    int t = threadIdx.x;
    int k0 = blockIdx.x * 64, n0 = blockIdx.y * 64;
    int tx = t & 15, ty = t >> 4;
    float acc[4][4];
#pragma unroll
    for (int i = 0; i < 4; i++)
#pragma unroll
        for (int j = 0; j < 4; j++) acc[i][j] = 0.f;
    for (int m0 = 0; m0 < Mr; m0 += 16) {
        __syncthreads();
        for (int idx = t; idx < 1024; idx += 256) {
            int mm = idx >> 6, c = idx & 63;
            As[mm][c] = (k0 + c < K1) ? A[(size_t)(m0 + mm) * K1 + k0 + c] : 0.f;
        }
        for (int idx = t; idx < 1024; idx += 256) {
            int mm = idx >> 6, c = idx & 63;
            Bs[mm][c] = (n0 + c < N) ? B[(size_t)(m0 + mm) * N + n0 + c] : 0.f;
        }
        __syncthreads();
#pragma unroll
        for (int mm = 0; mm < 16; mm++) {
            float4 av = *(const float4*)&As[mm][ty * 4];
            float4 bv = *(const float4*)&Bs[mm][tx * 4];
            float a4[4] = {av.x, av.y, av.z, av.w};
            float b4[4] = {bv.x, bv.y, bv.z, bv.w};
#pragma unroll
            for (int i = 0; i < 4; i++)
#pragma unroll
                for (int j = 0; j < 4; j++) acc[i][j] += a4[i] * b4[j];
        }
    }
#pragma unroll
    for (int i = 0; i < 4; i++) {
        int kr = k0 + ty * 4 + i;
        if (kr >= K1) continue;
        float d = divrow ? (1.f / (divrow[kr] + 1e-12f)) : 1.f;
#pragma unroll
        for (int j = 0; j < 4; j++) {
            int col = n0 + tx * 4 + j;
            if (col >= N) continue;
            C[(size_t)kr * N + col] = acc[i][j] * d;
        }
    }
}

// ---------------- edge mask GEMM: out[f][e] = sum_k P[r_e,k] P[c_e,k] Gsq[k,f] ----------------
// block: 64 edges x 128 features, 256 threads, k chunks of 32. EDGES % 64 == 0.
__global__ void k_mask(const float* __restrict__ P, int ldP, int K,
                       const float* __restrict__ Gsq,
                       const int* __restrict__ er, const int* __restrict__ ec,
                       float* __restrict__ out) {
    __shared__ __align__(16) float Gs[32][128];
    __shared__ __align__(16) float us[32][68];
    __shared__ int rr[64], cc[64];
    int t = threadIdx.x;
    int e0 = blockIdx.x * 64;
    if (t < 64) { rr[t] = er[e0 + t]; cc[t] = ec[e0 + t]; }
    float acc[8][4];
#pragma unroll
    for (int j = 0; j < 8; j++)
#pragma unroll
        for (int i = 0; i < 4; i++) acc[j][i] = 0.f;
    int le = (t & 15) * 4;   // 4 consecutive edges
    int lf = (t >> 4) * 8;   // 8 consecutive features
    for (int k0 = 0; k0 < K; k0 += 32) {
        __syncthreads();
        for (int idx = t; idx < 32 * 128; idx += 256) {
            int kk = idx >> 7, f = idx & 127;
            Gs[kk][f] = (k0 + kk < K) ? Gsq[(size_t)(k0 + kk) * FDIM + f] : 0.f;
        }
        for (int idx = t; idx < 64 * 32; idx += 256) {
            int kk = idx & 31, e = idx >> 5;
            float v = 0.f;
            if (k0 + kk < K)
                v = P[(size_t)rr[e] * ldP + k0 + kk] * P[(size_t)cc[e] * ldP + k0 + kk];
            us[kk][e] = v;
        }
        __syncthreads();
#pragma unroll
        for (int kk = 0; kk < 32; kk++) {
            float4 uv = *(const float4*)&us[kk][le];
            float4 ga = *(const float4*)&Gs[kk][lf];
            float4 gb = *(const float4*)&Gs[kk][lf + 4];
            float u4[4] = {uv.x, uv.y, uv.z, uv.w};
            float g8[8] = {ga.x, ga.y, ga.z, ga.w, gb.x, gb.y, gb.z, gb.w};
#pragma unroll
            for (int j = 0; j < 8; j++)
#pragma unroll
                for (int i = 0; i < 4; i++) acc[j][i] += g8[j] * u4[i];
        }
    }
#pragma unroll
    for (int j = 0; j < 8; j++) {
        float4 v = make_float4(acc[j][0], acc[j][1], acc[j][2], acc[j][3]);
        *(float4*)&out[(size_t)(lf + j) * EDGES + e0 + le] = v;
    }
}

// ---------------- per-edge sequential feature carry ----------------
__global__ void k_carry(const float* __restrict__ adj, float* __restrict__ out) {
    int e = blockIdx.x * blockDim.x + threadIdx.x;
    if (e >= EDGES) return;
    float a = adj[e];
#pragma unroll 8
    for (int f = 0; f < FDIM; f++) {
        float va = g_mA[(size_t)f * EDGES + e];
        float vb = g_mB[(size_t)f * EDGES + e];
        float tq = a * va;
        out[(size_t)f * EDGES + e] = tq + tq * vb;
        a = tq * vb;
    }
}

// ---------------- deterministic CSR build ----------------
__global__ void k_count(const int* __restrict__ er) {
    int e = blockIdx.x * blockDim.x + threadIdx.x;
    if (e < EDGES) atomicAdd(&g_cnt[er[e]], 1);
}

__global__ void k_scan() {   // one block, 1024 threads, n = N_NODES
    __shared__ int part[1024];
    const int n = N_NODES;
    const int per = (n + 1023) / 1024;
    int t = threadIdx.x;
    int s = 0;
    int lo = t * per, hi = min(n, (t + 1) * per);
    for (int i = lo; i < hi; i++) s += g_cnt[i];
    part[t] = s; __syncthreads();
    for (int off = 1; off < 1024; off <<= 1) {
        int v = (t >= off) ? part[t - off] : 0;
        __syncthreads();
        part[t] += v;
        __syncthreads();
    }
    int base = (t == 0) ? 0 : part[t - 1];
    for (int i = lo; i < hi; i++) {
        g_off[i] = base; g_cur[i] = base; base += g_cnt[i];
    }
    if (t == 1023) g_off[n] = base;
}

__global__ void k_scatter(const int* __restrict__ er) {
    int e = blockIdx.x * blockDim.x + threadIdx.x;
    if (e < EDGES) {
        int pos = atomicAdd(&g_cur[er[e]], 1);
        g_colS[pos] = e;   // edge index; sorted per row next
    }
}

__global__ void k_rowsort() {   // insertion sort each row segment by edge id (determinism)
    int r = blockIdx.x * blockDim.x + threadIdx.x;
    if (r >= N_NODES) return;
    int s = g_off[r], e = g_off[r + 1];
    for (int i = s + 1; i < e; i++) {
        int v = g_colS[i];
        int j = i - 1;
        while (j >= s && g_colS[j] > v) { g_colS[j + 1] = g_colS[j]; j--; }
        g_colS[j + 1] = v;
    }
}

__global__ void k_fill(const int* __restrict__ ec, const float* __restrict__ nv) {
    int i = blockIdx.x * blockDim.x + threadIdx.x;
    if (i < EDGES) {
        int e = g_colS[i];
        g_wS[i] = nv[e];
        g_colS[i] = ec[e];
    }
}

// ---------------- one propagation step: xout[r] = sum w * xin[col] ----------------
__global__ void k_prop(const float* __restrict__ xin, float* __restrict__ xout) {
    int r = blockIdx.x;
    int f = threadIdx.x;   // 128
    float acc = 0.f;
    int s = g_off[r], e = g_off[r + 1];
    for (int i = s; i < e; i++) {
        int c = g_colS[i];
        float w = g_wS[i];
        acc += w * xin[(size_t)c * FDIM + f];
    }
    xout[(size_t)r * FDIM + f] = acc;
}

// ---------------- final logits + log_softmax (fused, warp per row) ----------------
__global__ void k_final(const float* __restrict__ h, const float* __restrict__ W,
                        const float* __restrict__ b, float* __restrict__ out) {
    int warp = (blockIdx.x * blockDim.x + threadIdx.x) >> 5;
    int lane = threadIdx.x & 31;
    if (warp >= N_NODES) return;
    float p0 = 0.f, p1 = 0.f;
#pragma unroll
    for (int j = 0; j < 4; j++) {
        int k = lane + 32 * j;
        float hv = h[(size_t)warp * FDIM + k];
        p0 += hv * W[k * 2];
        p1 += hv * W[k * 2 + 1];
    }
    for (int o = 16; o; o >>= 1) {
        p0 += __shfl_down_sync(0xFFFFFFFFu, p0, o);
        p1 += __shfl_down_sync(0xFFFFFFFFu, p1, o);
    }
    if (lane == 0) {
        float l0 = p0 + b[0], l1 = p1 + b[1];
        float m = fmaxf(l0, l1);
        float ls = m + logf(expf(l0 - m) + expf(l1 - m));
        out[warp * 2]     = l0 - ls;
        out[warp * 2 + 1] = l1 - ls;
    }
}

// ================= host launcher =================
#define GSYM(var, sym) float* var; { void* _p = 0; cudaGetSymbolAddress(&_p, sym); var = (float*)_p; }

extern "C" void kernel_launch(void* const* d_in, const int* in_sizes, int n_in,
                              void* d_out, int out_size) {
    const float* x    = (const float*)d_in[0];
    const float* xcov = (const float*)d_in[1];
    const int*   er   = (const int*)d_in[2];
    const int*   ec   = (const int*)d_in[3];
    const float* adjv = (const float*)d_in[4];
    const float* nv   = (const float*)d_in[5];
    const float* gam  = (const float*)d_in[6];
    const float* bet  = (const float*)d_in[7];
    const float* c0W1 = (const float*)d_in[8];
    const float* c0b1 = (const float*)d_in[9];
    const float* c0W2 = (const float*)d_in[10];
    const float* c0b2 = (const float*)d_in[11];
    const float* c1W1 = (const float*)d_in[12];
    const float* c1b1 = (const float*)d_in[13];
    const float* c1W2 = (const float*)d_in[14];
    const float* c1b2 = (const float*)d_in[15];
    // c2_* (d_in[16..19]) are dead code in the reference
    const float* mW1 = (const float*)d_in[20];
    const float* mb1 = (const float*)d_in[21];
    const float* a1  = (const float*)d_in[22];
    const float* mW2 = (const float*)d_in[23];
    const float* mb2 = (const float*)d_in[24];
    const float* a2  = (const float*)d_in[25];
    const float* mW3 = (const float*)d_in[26];
    const float* mb3 = (const float*)d_in[27];

    float* outLog = (float*)d_out;
    float* outAdj = (float*)d_out + (size_t)N_NODES * 2;

    GSYM(xbn, g_xbn)   GSYM(xp0, g_xp0)   GSYM(xp1, g_xp1)
    GSYM(h,   g_h)     GSYM(h2,  g_h2)    GSYM(S0,  g_S0)
    GSYM(corr0, g_corr0) GSYM(cs0, g_colsum0) GSYM(cs1, g_colsum1)
    GSYM(xc1, g_xc1)   GSYM(corr1, g_corr1) GSYM(T0, g_T0) GSYM(G0, g_G0)
    GSYM(S1,  g_S1)    GSYM(xc2, g_xc2)   GSYM(corr2, g_corr2)
    GSYM(T1,  g_T1)    GSYM(G1,  g_G1)    GSYM(P1,  g_P1)
    GSYM(csA, g_csA)   GSYM(cssA, g_cssA)
    void* cntp = 0; cudaGetSymbolAddress(&cntp, g_cnt);

    // ---- BatchNorm(x) -> xbn ----
    cudaMemsetAsync(csA, 0, FDIM * 4, 0);
    cudaMemsetAsync(cssA, 0, FDIM * 4, 0);
    k_colsum<<<64, 128>>>(x, N_NODES, FDIM, 125, csA);
    k_colcss<<<64, 128>>>(x, N_NODES, FDIM, 125, csA, cssA);
    k_bn<<<(N_NODES * FDIM + 255) / 256, 256>>>(x, csA, cssA, gam, bet, xbn);

    // ---- corr0 = node_corr(x_cov) ----
    cudaMemsetAsync(csA, 0, FDIM * 4, 0);
    cudaMemsetAsync(cssA, 0, FDIM * 4, 0);
    k_colsum<<<64, 128>>>(xcov, N_NODES, FDIM, 125, csA);
    k_colcss<<<64, 128>>>(xcov, N_NODES, FDIM, 125, csA, cssA);
    k_corr<<<N_NODES, 128>>>(xcov, N_NODES, csA, cssA, corr0);

    // ---- level 0 cluster ----
    k_gemm_nn<<<dim3(125, 2), 256>>>(N_NODES, FDIM, FDIM, xcov, c0W1, c0b1, h, 1, 0);
    k_gemm_nn<<<dim3(125, 7), 256>>>(N_NODES, C0, FDIM, h, c0W2, c0b2, S0, 0, 0);
    k_softmax<<<N_NODES, 128>>>(S0, C0);
    cudaMemsetAsync(cs0, 0, C0 * 4, 0);
    k_colsum<<<64, 128>>>(S0, N_NODES, C0, 125, cs0);
    k_gemm_tn<<<dim3(7, 2), 256>>>(N_NODES, C0, FDIM, S0, xcov, xc1, cs0);
    k_gemm_tn<<<dim3(7, 2), 256>>>(N_NODES, C0, FDIM, S0, corr0, T0, 0);

    // ---- corr1 = node_corr(xc1); gains0 ----
    cudaMemsetAsync(csA, 0, FDIM * 4, 0);
    cudaMemsetAsync(cssA, 0, FDIM * 4, 0);
    k_colsum<<<4, 128>>>(xc1, C0, FDIM, 100, csA);
    k_colcss<<<4, 128>>>(xc1, C0, FDIM, 100, csA, cssA);
    k_corr<<<C0, 128>>>(xc1, C0, csA, cssA, corr1);
    k_gains<<<(C0 * FDIM + 255) / 256, 256>>>(corr1, T0, G0, C0 * FDIM);

    // ---- level 1 cluster ----
    k_gemm_nn<<<dim3(7, 2), 256>>>(C0, FDIM, FDIM, xc1, c1W1, c1b1, h, 1, 0);
    k_gemm_nn<<<dim3(7, 1), 256>>>(C0, C1, FDIM, h, c1W2, c1b2, S1, 0, 0);
    k_softmax<<<C0, 32>>>(S1, C1);
    cudaMemsetAsync(cs1, 0, C1 * 4, 0);
    k_colsum<<<4, 32>>>(S1, C0, C1, 100, cs1);
    k_gemm_tn<<<dim3(1, 2), 256>>>(C0, C1, FDIM, S1, xc1, xc2, cs1);
    k_gemm_tn<<<dim3(1, 2), 256>>>(C0, C1, FDIM, S1, corr1, T1, 0);

    // ---- corr2 = node_corr(xc2); gains1 ----
    cudaMemsetAsync(csA, 0, FDIM * 4, 0);
    cudaMemsetAsync(cssA, 0, FDIM * 4, 0);
    k_colsum<<<1, 128>>>(xc2, C1, FDIM, C1, csA);
    k_colcss<<<1, 128>>>(xc2, C1, FDIM, C1, csA, cssA);
    k_corr<<<C1, 128>>>(xc2, C1, csA, cssA, corr2);
    k_gains<<<(C1 * FDIM + 255) / 256, 256>>>(corr2, T1, G1, C1 * FDIM);

    // ---- projector P1 = S0 @ S1 ----
    k_gemm_nn<<<dim3(125, 1), 256>>>(N_NODES, C1, C0, S0, S1, 0, P1, 0, 0);

    // ---- edge masks (f-major) + carry -> adjs output ----
    {
        void* pA = 0; cudaGetSymbolAddress(&pA, g_mA);
        void* pB = 0; cudaGetSymbolAddress(&pB, g_mB);
        k_mask<<<EDGES / 64, 256>>>(P1, C1, C1, G1, er, ec, (float*)pA);
        k_mask<<<EDGES / 64, 256>>>(S0, C0, C0, G0, er, ec, (float*)pB);
    }
    k_carry<<<EDGES / 256, 256>>>(adjv, outAdj);

    // ---- CSR build (deterministic) ----
    cudaMemsetAsync(cntp, 0, N_NODES * 4, 0);
    k_count<<<EDGES / 256, 256>>>(er);
    k_scan<<<1, 1024>>>();
    k_scatter<<<EDGES / 256, 256>>>(er);
    k_rowsort<<<(N_NODES + 127) / 128, 128>>>();
    k_fill<<<EDGES / 256, 256>>>(ec, nv);

    // ---- propagation x <- A_norm @ x, K=10 ----
    cudaMemcpyAsync(xp0, xbn, (size_t)N_NODES * FDIM * 4, cudaMemcpyDeviceToDevice, 0);
    for (int it = 0; it < 10; it++) {
        const float* in  = (it & 1) ? xp1 : xp0;
        float*       out = (it & 1) ? xp0 : xp1;
        k_prop<<<N_NODES, 128>>>(in, out);
    }
    // 10 steps -> result back in xp0

    // ---- MLP + log_softmax ----
    k_gemm_nn<<<dim3(125, 2), 256>>>(N_NODES, FDIM, FDIM, xp0, mW1, mb1, h, 2, a1);
    k_gemm_nn<<<dim3(125, 2), 256>>>(N_NODES, FDIM, FDIM, h, mW2, mb2, h2, 2, a2);
    k_final<<<(N_NODES * 32 + 255) / 256, 256>>>(h2, mW3, mb3, outLog);

    (void)in_sizes; (void)n_in; (void)out_size;
}

// round 3
// speedup vs baseline: 1.0525x; 1.0525x over previous
#include <cuda_runtime.h>
#include <math.h>

#define N_NODES 8000
#define FDIM    128
#define EDGES   256000
#define C0      400
#define C1      20

// ---------------- static device scratch (no runtime allocation) ----------------
__device__ float g_xbn[N_NODES*FDIM];
__device__ float g_xp0[N_NODES*FDIM];
__device__ float g_xp1[N_NODES*FDIM];
__device__ float g_h  [N_NODES*FDIM];
__device__ float g_h2 [N_NODES*FDIM];
__device__ float g_S0 [N_NODES*C0];
__device__ float g_corr0[N_NODES*FDIM];
__device__ float g_colsum0[C0];
__device__ float g_colsum1[C1];
__device__ float g_xc1  [C0*FDIM];
__device__ float g_corr1[C0*FDIM];
__device__ float g_T0   [C0*FDIM];
__device__ float g_G0   [C0*FDIM];
__device__ float g_S1   [C0*C1];
__device__ float g_xc2  [C1*FDIM];
__device__ float g_corr2[C1*FDIM];
__device__ float g_T1   [C1*FDIM];
__device__ float g_G1   [C1*FDIM];
__device__ float g_P1   [N_NODES*C1];
__device__ float g_csA  [C0];
__device__ float g_cssA [C0];
__device__ int   g_cnt[N_NODES];
__device__ int   g_off[N_NODES+1];
__device__ int   g_cur[N_NODES];
__device__ int   g_colS[EDGES];
__device__ float g_wS  [EDGES];
__device__ float g_mA[(size_t)FDIM*EDGES];   // f-major [F][E], k=20 mask
__device__ float g_mB[(size_t)FDIM*EDGES];   // f-major [F][E], k=400 mask

// ---------------- column reductions (atomic partials) ----------------
__global__ void k_colsum(const float* __restrict__ A, int n, int c, int rowsPer,
                         float* __restrict__ out) {
    int r0 = blockIdx.x * rowsPer;
    int r1 = min(n, r0 + rowsPer);
    for (int col = threadIdx.x; col < c; col += blockDim.x) {
        float s = 0.f;
        for (int r = r0; r < r1; r++) s += A[(size_t)r * c + col];
        atomicAdd(&out[col], s);
    }
}

__global__ void k_colcss(const float* __restrict__ A, int n, int c, int rowsPer,
                         const float* __restrict__ colsum, float* __restrict__ out) {
    int r0 = blockIdx.x * rowsPer;
    int r1 = min(n, r0 + rowsPer);
    for (int col = threadIdx.x; col < c; col += blockDim.x) {
        float m = colsum[col] / (float)n;
        float s = 0.f;
        for (int r = r0; r < r1; r++) {
            float d = A[(size_t)r * c + col] - m;
            s += d * d;
        }
        atomicAdd(&out[col], s);
    }
}

// ---------------- batchnorm apply ----------------
__global__ void k_bn(const float* __restrict__ x, const float* __restrict__ cs,
                     const float* __restrict__ css, const float* __restrict__ gam,
                     const float* __restrict__ bet, float* __restrict__ o) {
    int i = blockIdx.x * blockDim.x + threadIdx.x;
    if (i >= N_NODES * FDIM) return;
    int f = i & (FDIM - 1);
    float mu  = cs[f]  * (1.f / N_NODES);
    float var = css[f] * (1.f / N_NODES);
    o[i] = (x[i] - mu) * rsqrtf(var + 1e-5f) * gam[f] + bet[f];
}

// ---------------- node correlation: out[n,f] = zc_n[f] * sum_f' zc_n[f'] ----------------
__global__ void k_corr(const float* __restrict__ z, int n,
                       const float* __restrict__ cs, const float* __restrict__ css,
                       float* __restrict__ out) {
    int r = blockIdx.x, f = threadIdx.x;   // 128 threads
    float mean = cs[f] / (float)n;
    float inv  = 1.f / (sqrtf(css[f]) + 1e-12f);
    float v = (z[(size_t)r * FDIM + f] - mean) * inv;
    __shared__ float red[128];
    red[f] = v; __syncthreads();
    for (int s = 64; s > 0; s >>= 1) {
        if (f < s) red[f] += red[f + s];
        __syncthreads();
    }
    out[(size_t)r * FDIM + f] = v * red[0];
}

// ---------------- row softmax (in place) ----------------
__global__ void k_softmax(float* __restrict__ X, int W) {
    int r = blockIdx.x;
    float* row = X + (size_t)r * W;
    int t = threadIdx.x, bd = blockDim.x;
    __shared__ float red[128];
    float m = -3.4e38f;
    for (int c = t; c < W; c += bd) m = fmaxf(m, row[c]);
    red[t] = m; __syncthreads();
    for (int s = bd >> 1; s > 0; s >>= 1) {
        if (t < s) red[t] = fmaxf(red[t], red[t + s]);
        __syncthreads();
    }
    m = red[0]; __syncthreads();
    float sum = 0.f;
    for (int c = t; c < W; c += bd) { float e = expf(row[c] - m); row[c] = e; sum += e; }
    red[t] = sum; __syncthreads();
    for (int s = bd >> 1; s > 0; s >>= 1) {
        if (t < s) red[t] += red[t + s];
        __syncthreads();
    }
    float inv = 1.f / red[0];
    for (int c = t; c < W; c += bd) row[c] *= inv;
}

// ---------------- gains: g = sigmoid(c - t); store g*g ----------------
__global__ void k_gains(const float* __restrict__ c, const float* __restrict__ t,
                        float* __restrict__ g, int n) {
    int i = blockIdx.x * blockDim.x + threadIdx.x;
    if (i < n) {
        float x = 1.f / (1.f + expf(t[i] - c[i]));
        g[i] = x * x;
    }
}

// ---------------- generic tiled GEMM: C = act(A@B + bias) ----------------
// A [M,K] rm, B [K,N] rm. K % 16 == 0. act: 0 none, 1 relu, 2 prelu(aux[0]).
__global__ void k_gemm_nn(int M, int N, int K,
                          const float* __restrict__ A, const float* __restrict__ B,
                          const float* __restrict__ bias, float* __restrict__ C,
                          int act, const float* __restrict__ aux) {
    __shared__ __align__(16) float As[16][68];
    __shared__ __align__(16) float Bs[16][64];
    int t = threadIdx.x;
    int m0 = blockIdx.x * 64, n0 = blockIdx.y * 64;
    int tx = t & 15, ty = t >> 4;
    float acc[4][4];
#pragma unroll
    for (int i = 0; i < 4; i++)
#pragma unroll
        for (int j = 0; j < 4; j++) acc[i][j] = 0.f;
    for (int k0 = 0; k0 < K; k0 += 16) {
        __syncthreads();
        for (int idx = t; idx < 1024; idx += 256) {
            int kk = idx & 15, r = idx >> 4;
            int row = m0 + r;
            As[kk][r] = (row < M) ? A[(size_t)row * K + k0 + kk] : 0.f;
        }
        for (int idx = t; idx < 1024; idx += 256) {
            int kk = idx >> 6, c = idx & 63;
            int col = n0 + c;
            Bs[kk][c] = (col < N) ? B[(size_t)(k0 + kk) * N + col] : 0.f;
        }
        __syncthreads();
#pragma unroll
        for (int kk = 0; kk < 16; kk++) {
            float4 av = *(const float4*)&As[kk][ty * 4];
            float4 bv = *(const float4*)&Bs[kk][tx * 4];
            float a4[4] = {av.x, av.y, av.z, av.w};
            float b4[4] = {bv.x, bv.y, bv.z, bv.w};
#pragma unroll
            for (int i = 0; i < 4; i++)
#pragma unroll
                for (int j = 0; j < 4; j++) acc[i][j] += a4[i] * b4[j];
        }
    }
    float slope = (act == 2) ? aux[0] : 0.f;
#pragma unroll
    for (int i = 0; i < 4; i++) {
        int row = m0 + ty * 4 + i;
        if (row >= M) continue;
#pragma unroll
        for (int j = 0; j < 4; j++) {
            int col = n0 + tx * 4 + j;
            if (col >= N) continue;
            float v = acc[i][j];
            if (bias) v += bias[col];
            if (act == 1) v = fmaxf(v, 0.f);
            else if (act == 2) v = (v >= 0.f) ? v : slope * v;
            C[(size_t)row * N + col] = v;
        }
    }
}

// ---------------- GEMM C = A^T @ B, optional per-row divide ----------------
// A [Mr,K1] rm, B [Mr,N] rm, C [K1,N]. Mr % 16 == 0.
__global__ void k_gemm_tn(int Mr, int K1, int N,
                          const float* __restrict__ A, const float* __restrict__ B,
                          float* __restrict__ C, const float* __restrict__ divrow) {
    __shared__ __align__(16) float As[16][64];
    __shared__ __align__(16) float Bs[16][64];
    int t = threadIdx.x;
    int k0 = blockIdx.x * 64, n0 = blockIdx.y * 64;
    int tx = t & 15, ty = t >> 4;
    float acc[4][4];
#pragma unroll
    for (int i = 0; i < 4; i++)
#pragma unroll
        for (int j = 0; j < 4; j++) acc[i][j] = 0.f;
    for (int m0 = 0; m0 < Mr; m0 += 16) {
        __syncthreads();
        for (int idx = t; idx < 1024; idx += 256) {
            int mm = idx >> 6, c = idx & 63;
            As[mm][c] = (k0 + c < K1) ? A[(size_t)(m0 + mm) * K1 + k0 + c] : 0.f;
        }
        for (int idx = t; idx < 1024; idx += 256) {
            int mm = idx >> 6, c = idx & 63;
            Bs[mm][c] = (n0 + c < N) ? B[(size_t)(m0 + mm) * N + n0 + c] : 0.f;
        }
        __syncthreads();
#pragma unroll
        for (int mm = 0; mm < 16; mm++) {
            float4 av = *(const float4*)&As[mm][ty * 4];
            float4 bv = *(const float4*)&Bs[mm][tx * 4];
            float a4[4] = {av.x, av.y, av.z, av.w};
            float b4[4] = {bv.x, bv.y, bv.z, bv.w};
#pragma unroll
            for (int i = 0; i < 4; i++)
#pragma unroll
                for (int j = 0; j < 4; j++) acc[i][j] += a4[i] * b4[j];
        }
    }
#pragma unroll
    for (int i = 0; i < 4; i++) {
        int kr = k0 + ty * 4 + i;
        if (kr >= K1) continue;
        float d = divrow ? (1.f / (divrow[kr] + 1e-12f)) : 1.f;
#pragma unroll
        for (int j = 0; j < 4; j++) {
            int col = n0 + tx * 4 + j;
            if (col >= N) continue;
            C[(size_t)kr * N + col] = acc[i][j] * d;
        }
    }
}

// ---------------- tf32 helper ----------------
__device__ __forceinline__ unsigned tf32r(float x) {
    unsigned u;
    asm("cvt.rna.tf32.f32 %0, %1;" : "=r"(u) : "f"(x));
    return u;
}

// ---------------- edge mask GEMM via tf32 tensor cores ----------------
// out[f][e] = sum_k P[r_e,k] P[c_e,k] Gsq[k,f]
// CTA: 128 edges x 128 features, 256 threads (8 warps).
// Warp w computes rows [w*16, w*16+16) x all 128 features (16 n-tiles of m16n8k8).
__global__ void k_mask_mma(const float* __restrict__ P, int ldP, int K,
                           const float* __restrict__ Gsq,
                           const int* __restrict__ er, const int* __restrict__ ec,
                           float* __restrict__ out) {
    __shared__ unsigned Us[128][36];   // [edge][k], pad 36 -> conflict-free A frags
    __shared__ unsigned Gs[32][136];   // [k][feat], pad 136 -> conflict-free B frags
    __shared__ int rr[128], cc[128];
    int t = threadIdx.x, lane = t & 31, w = t >> 5;
    int e0 = blockIdx.x * 128;
    if (t < 128) { rr[t] = er[e0 + t]; cc[t] = ec[e0 + t]; }
    float acc[16][4];
#pragma unroll
    for (int nt = 0; nt < 16; nt++)
#pragma unroll
        for (int i = 0; i < 4; i++) acc[nt][i] = 0.f;
    __syncthreads();

    for (int k0 = 0; k0 < K; k0 += 32) {
        // stage G chunk [32 x 128] (tf32-rounded)
        for (int idx = t; idx < 32 * 128; idx += 256) {
            int kk = idx >> 7, f = idx & 127;
            float v = (k0 + kk < K) ? Gsq[(size_t)(k0 + kk) * FDIM + f] : 0.f;
            Gs[kk][f] = tf32r(v);
        }
        // stage U chunk [128 edges x 32 k]: u = P[r,k]*P[c,k] (tf32-rounded)
        for (int idx = t; idx < 128 * 32; idx += 256) {
            int kk = idx & 31, e = idx >> 5;
            float v = 0.f;
            if (k0 + kk < K)
                v = P[(size_t)rr[e] * ldP + k0 + kk] * P[(size_t)cc[e] * ldP + k0 + kk];
            Us[e][kk] = tf32r(v);
        }
        __syncthreads();
#pragma unroll
        for (int ks = 0; ks < 4; ks++) {
            int kb = ks * 8;
            int ar = w * 16 + (lane >> 2);
            int ak = kb + (lane & 3);
            unsigned a0 = Us[ar][ak];
            unsigned a1 = Us[ar + 8][ak];
            unsigned a2 = Us[ar][ak + 4];
            unsigned a3 = Us[ar + 8][ak + 4];
#pragma unroll
            for (int nt = 0; nt < 16; nt++) {
                int bn = nt * 8 + (lane >> 2);
                unsigned b0 = Gs[kb + (lane & 3)][bn];
                unsigned b1 = Gs[kb + (lane & 3) + 4][bn];
                asm volatile(
                    "mma.sync.aligned.m16n8k8.row.col.f32.tf32.tf32.f32 "
                    "{%0,%1,%2,%3}, {%4,%5,%6,%7}, {%8,%9}, {%0,%1,%2,%3};"
                    : "+f"(acc[nt][0]), "+f"(acc[nt][1]),
                      "+f"(acc[nt][2]), "+f"(acc[nt][3])
                    : "r"(a0), "r"(a1), "r"(a2), "r"(a3), "r"(b0), "r"(b1));
            }
        }
        __syncthreads();
    }
    // epilogue: f-major writes. c0:(r, c) c1:(r, c+1) c2:(r+8, c) c3:(r+8, c+1)
    int r = w * 16 + (lane >> 2);
    int cb = 2 * (lane & 3);
#pragma unroll
    for (int nt = 0; nt < 16; nt++) {
        int c = nt * 8 + cb;
        size_t base = (size_t)c * EDGES + e0;
        out[base + r]              = acc[nt][0];
        out[base + EDGES + r]      = acc[nt][1];
        out[base + r + 8]          = acc[nt][2];
        out[base + EDGES + r + 8]  = acc[nt][3];
    }
}

// ---------------- per-edge sequential feature carry ----------------
__global__ void k_carry(const float* __restrict__ adj, float* __restrict__ out) {
    int e = blockIdx.x * blockDim.x + threadIdx.x;
    if (e >= EDGES) return;
    float a = adj[e];
#pragma unroll 8
    for (int f = 0; f < FDIM; f++) {
        float va = g_mA[(size_t)f * EDGES + e];
        float vb = g_mB[(size_t)f * EDGES + e];
        float tq = a * va;
        out[(size_t)f * EDGES + e] = tq + tq * vb;
        a = tq * vb;
    }
}

// ---------------- deterministic CSR build ----------------
__global__ void k_count(const int* __restrict__ er) {
    int e = blockIdx.x * blockDim.x + threadIdx.x;
    if (e < EDGES) atomicAdd(&g_cnt[er[e]], 1);
}

__global__ void k_scan() {   // one block, 1024 threads
    __shared__ int part[1024];
    const int n = N_NODES;
    const int per = (n + 1023) / 1024;
    int t = threadIdx.x;
    int s = 0;
    int lo = t * per, hi = min(n, (t + 1) * per);
    for (int i = lo; i < hi; i++) s += g_cnt[i];
    part[t] = s; __syncthreads();
    for (int off = 1; off < 1024; off <<= 1) {
        int v = (t >= off) ? part[t - off] : 0;
        __syncthreads();
        part[t] += v;
        __syncthreads();
    }
    int base = (t == 0) ? 0 : part[t - 1];
    for (int i = lo; i < hi; i++) {
        g_off[i] = base; g_cur[i] = base; base += g_cnt[i];
    }
    if (t == 1023) g_off[n] = base;
}

__global__ void k_scatter(const int* __restrict__ er) {
    int e = blockIdx.x * blockDim.x + threadIdx.x;
    if (e < EDGES) {
        int pos = atomicAdd(&g_cur[er[e]], 1);
        g_colS[pos] = e;
    }
}

__global__ void k_rowsort() {
    int r = blockIdx.x * blockDim.x + threadIdx.x;
    if (r >= N_NODES) return;
    int s = g_off[r], e = g_off[r + 1];
    for (int i = s + 1; i < e; i++) {
        int v = g_colS[i];
        int j = i - 1;
        while (j >= s && g_colS[j] > v) { g_colS[j + 1] = g_colS[j]; j--; }
        g_colS[j + 1] = v;
    }
}

__global__ void k_fill(const int* __restrict__ ec, const float* __restrict__ nv) {
    int i = blockIdx.x * blockDim.x + threadIdx.x;
    if (i < EDGES) {
        int e = g_colS[i];
        g_wS[i] = nv[e];
        g_colS[i] = ec[e];
    }
}

// ---------------- one propagation step ----------------
__global__ void k_prop(const float* __restrict__ xin, float* __restrict__ xout) {
    int r = blockIdx.x;
    int f = threadIdx.x;
    float acc = 0.f;
    int s = g_off[r], e = g_off[r + 1];
    for (int i = s; i < e; i++) {
        int c = g_colS[i];
        float w = g_wS[i];
        acc += w * xin[(size_t)c * FDIM + f];
    }
    xout[(size_t)r * FDIM + f] = acc;
}

// ---------------- final logits + log_softmax ----------------
__global__ void k_final(const float* __restrict__ h, const float* __restrict__ W,
                        const float* __restrict__ b, float* __restrict__ out) {
    int warp = (blockIdx.x * blockDim.x + threadIdx.x) >> 5;
    int lane = threadIdx.x & 31;
    if (warp >= N_NODES) return;
    float p0 = 0.f, p1 = 0.f;
#pragma unroll
    for (int j = 0; j < 4; j++) {
        int k = lane + 32 * j;
        float hv = h[(size_t)warp * FDIM + k];
        p0 += hv * W[k * 2];
        p1 += hv * W[k * 2 + 1];
    }
    for (int o = 16; o; o >>= 1) {
        p0 += __shfl_down_sync(0xFFFFFFFFu, p0, o);
        p1 += __shfl_down_sync(0xFFFFFFFFu, p1, o);
    }
    if (lane == 0) {
        float l0 = p0 + b[0], l1 = p1 + b[1];
        float m = fmaxf(l0, l1);
        float ls = m + logf(expf(l0 - m) + expf(l1 - m));
        out[warp * 2]     = l0 - ls;
        out[warp * 2 + 1] = l1 - ls;
    }
}

// ================= host launcher =================
#define GSYM(var, sym) float* var; { void* _p = 0; cudaGetSymbolAddress(&_p, sym); var = (float*)_p; }

extern "C" void kernel_launch(void* const* d_in, const int* in_sizes, int n_in,
                              void* d_out, int out_size) {
    const float* x    = (const float*)d_in[0];
    const float* xcov = (const float*)d_in[1];
    const int*   er   = (const int*)d_in[2];
    const int*   ec   = (const int*)d_in[3];
    const float* adjv = (const float*)d_in[4];
    const float* nv   = (const float*)d_in[5];
    const float* gam  = (const float*)d_in[6];
    const float* bet  = (const float*)d_in[7];
    const float* c0W1 = (const float*)d_in[8];
    const float* c0b1 = (const float*)d_in[9];
    const float* c0W2 = (const float*)d_in[10];
    const float* c0b2 = (const float*)d_in[11];
    const float* c1W1 = (const float*)d_in[12];
    const float* c1b1 = (const float*)d_in[13];
    const float* c1W2 = (const float*)d_in[14];
    const float* c1b2 = (const float*)d_in[15];
    // c2_* (d_in[16..19]) are dead code in the reference
    const float* mW1 = (const float*)d_in[20];
    const float* mb1 = (const float*)d_in[21];
    const float* a1  = (const float*)d_in[22];
    const float* mW2 = (const float*)d_in[23];
    const float* mb2 = (const float*)d_in[24];
    const float* a2  = (const float*)d_in[25];
    const float* mW3 = (const float*)d_in[26];
    const float* mb3 = (const float*)d_in[27];

    float* outLog = (float*)d_out;
    float* outAdj = (float*)d_out + (size_t)N_NODES * 2;

    GSYM(xbn, g_xbn)   GSYM(xp0, g_xp0)   GSYM(xp1, g_xp1)
    GSYM(h,   g_h)     GSYM(h2,  g_h2)    GSYM(S0,  g_S0)
    GSYM(corr0, g_corr0) GSYM(cs0, g_colsum0) GSYM(cs1, g_colsum1)
    GSYM(xc1, g_xc1)   GSYM(corr1, g_corr1) GSYM(T0, g_T0) GSYM(G0, g_G0)
    GSYM(S1,  g_S1)    GSYM(xc2, g_xc2)   GSYM(corr2, g_corr2)
    GSYM(T1,  g_T1)    GSYM(G1,  g_G1)    GSYM(P1,  g_P1)
    GSYM(csA, g_csA)   GSYM(cssA, g_cssA)
    void* cntp = 0; cudaGetSymbolAddress(&cntp, g_cnt);

    // ---- BatchNorm(x) -> xbn ----
    cudaMemsetAsync(csA, 0, FDIM * 4, 0);
    cudaMemsetAsync(cssA, 0, FDIM * 4, 0);
    k_colsum<<<64, 128>>>(x, N_NODES, FDIM, 125, csA);
    k_colcss<<<64, 128>>>(x, N_NODES, FDIM, 125, csA, cssA);
    k_bn<<<(N_NODES * FDIM + 255) / 256, 256>>>(x, csA, cssA, gam, bet, xbn);

    // ---- corr0 = node_corr(x_cov) ----
    cudaMemsetAsync(csA, 0, FDIM * 4, 0);
    cudaMemsetAsync(cssA, 0, FDIM * 4, 0);
    k_colsum<<<64, 128>>>(xcov, N_NODES, FDIM, 125, csA);
    k_colcss<<<64, 128>>>(xcov, N_NODES, FDIM, 125, csA, cssA);
    k_corr<<<N_NODES, 128>>>(xcov, N_NODES, csA, cssA, corr0);

    // ---- level 0 cluster ----
    k_gemm_nn<<<dim3(125, 2), 256>>>(N_NODES, FDIM, FDIM, xcov, c0W1, c0b1, h, 1, 0);
    k_gemm_nn<<<dim3(125, 7), 256>>>(N_NODES, C0, FDIM, h, c0W2, c0b2, S0, 0, 0);
    k_softmax<<<N_NODES, 128>>>(S0, C0);
    cudaMemsetAsync(cs0, 0, C0 * 4, 0);
    k_colsum<<<64, 128>>>(S0, N_NODES, C0, 125, cs0);
    k_gemm_tn<<<dim3(7, 2), 256>>>(N_NODES, C0, FDIM, S0, xcov, xc1, cs0);
    k_gemm_tn<<<dim3(7, 2), 256>>>(N_NODES, C0, FDIM, S0, corr0, T0, 0);

    // ---- corr1 = node_corr(xc1); gains0 ----
    cudaMemsetAsync(csA, 0, FDIM * 4, 0);
    cudaMemsetAsync(cssA, 0, FDIM * 4, 0);
    k_colsum<<<4, 128>>>(xc1, C0, FDIM, 100, csA);
    k_colcss<<<4, 128>>>(xc1, C0, FDIM, 100, csA, cssA);
    k_corr<<<C0, 128>>>(xc1, C0, csA, cssA, corr1);
    k_gains<<<(C0 * FDIM + 255) / 256, 256>>>(corr1, T0, G0, C0 * FDIM);

    // ---- level 1 cluster ----
    k_gemm_nn<<<dim3(7, 2), 256>>>(C0, FDIM, FDIM, xc1, c1W1, c1b1, h, 1, 0);
    k_gemm_nn<<<dim3(7, 1), 256>>>(C0, C1, FDIM, h, c1W2, c1b2, S1, 0, 0);
    k_softmax<<<C0, 32>>>(S1, C1);
    cudaMemsetAsync(cs1, 0, C1 * 4, 0);
    k_colsum<<<4, 32>>>(S1, C0, C1, 100, cs1);
    k_gemm_tn<<<dim3(1, 2), 256>>>(C0, C1, FDIM, S1, xc1, xc2, cs1);
    k_gemm_tn<<<dim3(1, 2), 256>>>(C0, C1, FDIM, S1, corr1, T1, 0);

    // ---- corr2 = node_corr(xc2); gains1 ----
    cudaMemsetAsync(csA, 0, FDIM * 4, 0);
    cudaMemsetAsync(cssA, 0, FDIM * 4, 0);
    k_colsum<<<1, 128>>>(xc2, C1, FDIM, C1, csA);
    k_colcss<<<1, 128>>>(xc2, C1, FDIM, C1, csA, cssA);
    k_corr<<<C1, 128>>>(xc2, C1, csA, cssA, corr2);
    k_gains<<<(C1 * FDIM + 255) / 256, 256>>>(corr2, T1, G1, C1 * FDIM);

    // ---- projector P1 = S0 @ S1 ----
    k_gemm_nn<<<dim3(125, 1), 256>>>(N_NODES, C1, C0, S0, S1, 0, P1, 0, 0);

    // ---- edge masks via tf32 MMA (f-major) + carry -> adjs output ----
    {
        void* pA = 0; cudaGetSymbolAddress(&pA, g_mA);
        void* pB = 0; cudaGetSymbolAddress(&pB, g_mB);
        k_mask_mma<<<EDGES / 128, 256>>>(P1, C1, C1, G1, er, ec, (float*)pA);
        k_mask_mma<<<EDGES / 128, 256>>>(S0, C0, C0, G0, er, ec, (float*)pB);
    }
    k_carry<<<EDGES / 256, 256>>>(adjv, outAdj);

    // ---- CSR build (deterministic) ----
    cudaMemsetAsync(cntp, 0, N_NODES * 4, 0);
    k_count<<<EDGES / 256, 256>>>(er);
    k_scan<<<1, 1024>>>();
    k_scatter<<<EDGES / 256, 256>>>(er);
    k_rowsort<<<(N_NODES + 127) / 128, 128>>>();
    k_fill<<<EDGES / 256, 256>>>(ec, nv);

    // ---- propagation x <- A_norm @ x, K=10 ----
    cudaMemcpyAsync(xp0, xbn, (size_t)N_NODES * FDIM * 4, cudaMemcpyDeviceToDevice, 0);
    for (int it = 0; it < 10; it++) {
        const float* in  = (it & 1) ? xp1 : xp0;
        float*       out = (it & 1) ? xp0 : xp1;
        k_prop<<<N_NODES, 128>>>(in, out);
    }

    // ---- MLP + log_softmax ----
    k_gemm_nn<<<dim3(125, 2), 256>>>(N_NODES, FDIM, FDIM, xp0, mW1, mb1, h, 2, a1);
    k_gemm_nn<<<dim3(125, 2), 256>>>(N_NODES, FDIM, FDIM, h, mW2, mb2, h2, 2, a2);
    k_final<<<(N_NODES * 32 + 255) / 256, 256>>>(h2, mW3, mb3, outLog);

    (void)in_sizes; (void)n_in; (void)out_size;
}

// round 4
// speedup vs baseline: 3.1797x; 3.0210x over previous
#include <cuda_runtime.h>
#include <math.h>

#define N_NODES 8000
#define FDIM    128
#define EDGES   256000
#define C0      400
#define C1      20

// ---------------- static device scratch (no runtime allocation) ----------------
__device__ float g_xbn[N_NODES*FDIM];
__device__ float g_xp0[N_NODES*FDIM];
__device__ float g_xp1[N_NODES*FDIM];
__device__ float g_hA [N_NODES*FDIM];    // chain A scratch (cluster MLPs)
__device__ float g_hB1[N_NODES*FDIM];    // chain B scratch (final MLP)
__device__ float g_hB2[N_NODES*FDIM];
__device__ float g_S0 [N_NODES*C0];
__device__ float g_corr0[N_NODES*FDIM];
__device__ float g_cs0[C0];
__device__ float g_cs1[C1];
__device__ float g_xc1  [C0*FDIM];
__device__ float g_corr1[C0*FDIM];
__device__ float g_T0   [C0*FDIM];
__device__ float g_G0   [C0*FDIM];
__device__ float g_S1   [C0*C1];
__device__ float g_xc2  [C1*FDIM];
__device__ float g_corr2[C1*FDIM];
__device__ float g_T1   [C1*FDIM];
__device__ float g_G1   [C1*FDIM];
__device__ float g_P1   [N_NODES*C1];
// stats buffers (chain A)
__device__ float g_pa1[250*C0];
__device__ float g_pa2[250*C0];
__device__ float g_csA[FDIM];
__device__ float g_cssA[FDIM];
__device__ float g_csB[FDIM];
__device__ float g_cssB[FDIM];
__device__ float g_csC[FDIM];
__device__ float g_cssC[FDIM];
// stats buffers (chain B)
__device__ float g_pb1[250*FDIM];
__device__ float g_pb2[250*FDIM];
__device__ float g_csX[FDIM];
__device__ float g_cssX[FDIM];
// split-K partials (chain A, reused sequentially)
__device__ float g_tnpart[20*C0*FDIM];
// CSR (chain B)
__device__ int   g_cnt[N_NODES];
__device__ int   g_off[N_NODES+1];
__device__ int   g_cur[N_NODES];
__device__ int   g_colS[EDGES];
__device__ float g_wS  [EDGES];

// ---------------- two-stage deterministic column stats ----------------
// partial sums (and optional sum of squares) over a row chunk
__global__ void k_psum(const float* __restrict__ A, int n, int c, int rowsPer,
                       float* __restrict__ ps, float* __restrict__ pq) {
    int b = blockIdx.x;
    int r0 = b * rowsPer, r1 = min(n, r0 + rowsPer);
    for (int col = threadIdx.x; col < c; col += blockDim.x) {
        float s = 0.f, q = 0.f;
        for (int r = r0; r < r1; r++) {
            float v = A[(size_t)r * c + col];
            s += v; q += v * v;
        }
        ps[(size_t)b * c + col] = s;
        if (pq) pq[(size_t)b * c + col] = q;
    }
}

// reduce partials: outS = col sums; outCss = centered sum of squares
__global__ void k_preduce(const float* __restrict__ ps, const float* __restrict__ pq,
                          int nb, int c, int n,
                          float* __restrict__ outS, float* __restrict__ outCss) {
    int col = blockIdx.x * blockDim.x + threadIdx.x;
    if (col >= c) return;
    float s = 0.f, q = 0.f;
    for (int b = 0; b < nb; b++) {
        s += ps[(size_t)b * c + col];
        if (pq) q += pq[(size_t)b * c + col];
    }
    outS[col] = s;
    if (outCss) outCss[col] = q - s * s / (float)n;
}

// ---------------- batchnorm apply ----------------
__global__ void k_bn(const float* __restrict__ x, const float* __restrict__ cs,
                     const float* __restrict__ css, const float* __restrict__ gam,
                     const float* __restrict__ bet, float* __restrict__ o) {
    int i = blockIdx.x * blockDim.x + threadIdx.x;
    if (i >= N_NODES * FDIM) return;
    int f = i & (FDIM - 1);
    float mu  = cs[f]  * (1.f / N_NODES);
    float var = css[f] * (1.f / N_NODES);
    o[i] = (x[i] - mu) * rsqrtf(var + 1e-5f) * gam[f] + bet[f];
}

// ---------------- node correlation ----------------
__global__ void k_corr(const float* __restrict__ z, int n,
                       const float* __restrict__ cs, const float* __restrict__ css,
                       float* __restrict__ out) {
    int r = blockIdx.x, f = threadIdx.x;   // 128 threads
    float mean = cs[f] / (float)n;
    float inv  = 1.f / (sqrtf(css[f]) + 1e-12f);
    float v = (z[(size_t)r * FDIM + f] - mean) * inv;
    __shared__ float red[128];
    red[f] = v; __syncthreads();
    for (int s = 64; s > 0; s >>= 1) {
        if (f < s) red[f] += red[f + s];
        __syncthreads();
    }
    out[(size_t)r * FDIM + f] = v * red[0];
}

// ---------------- row softmax (in place) ----------------
__global__ void k_softmax(float* __restrict__ X, int W) {
    int r = blockIdx.x;
    float* row = X + (size_t)r * W;
    int t = threadIdx.x, bd = blockDim.x;
    __shared__ float red[128];
    float m = -3.4e38f;
    for (int c = t; c < W; c += bd) m = fmaxf(m, row[c]);
    red[t] = m; __syncthreads();
    for (int s = bd >> 1; s > 0; s >>= 1) {
        if (t < s) red[t] = fmaxf(red[t], red[t + s]);
        __syncthreads();
    }
    m = red[0]; __syncthreads();
    float sum = 0.f;
    for (int c = t; c < W; c += bd) { float e = expf(row[c] - m); row[c] = e; sum += e; }
    red[t] = sum; __syncthreads();
    for (int s = bd >> 1; s > 0; s >>= 1) {
        if (t < s) red[t] += red[t + s];
        __syncthreads();
    }
    float inv = 1.f / red[0];
    for (int c = t; c < W; c += bd) row[c] *= inv;
}

// ---------------- gains: store sigmoid(c-t)^2 ----------------
__global__ void k_gains(const float* __restrict__ c, const float* __restrict__ t,
                        float* __restrict__ g, int n) {
    int i = blockIdx.x * blockDim.x + threadIdx.x;
    if (i < n) {
        float x = 1.f / (1.f + expf(t[i] - c[i]));
        g[i] = x * x;
    }
}

// ---------------- generic tiled GEMM: C = act(A@B + bias) ----------------
__global__ void k_gemm_nn(int M, int N, int K,
                          const float* __restrict__ A, const float* __restrict__ B,
                          const float* __restrict__ bias, float* __restrict__ C,
                          int act, const float* __restrict__ aux) {
    __shared__ __align__(16) float As[16][68];
    __shared__ __align__(16) float Bs[16][64];
    int t = threadIdx.x;
    int m0 = blockIdx.x * 64, n0 = blockIdx.y * 64;
    int tx = t & 15, ty = t >> 4;
    float acc[4][4];
#pragma unroll
    for (int i = 0; i < 4; i++)
#pragma unroll
        for (int j = 0; j < 4; j++) acc[i][j] = 0.f;
    for (int k0 = 0; k0 < K; k0 += 16) {
        __syncthreads();
        for (int idx = t; idx < 1024; idx += 256) {
            int kk = idx & 15, r = idx >> 4;
            int row = m0 + r;
            As[kk][r] = (row < M) ? A[(size_t)row * K + k0 + kk] : 0.f;
        }
        for (int idx = t; idx < 1024; idx += 256) {
            int kk = idx >> 6, c = idx & 63;
            int col = n0 + c;
            Bs[kk][c] = (col < N) ? B[(size_t)(k0 + kk) * N + col] : 0.f;
        }
        __syncthreads();
#pragma unroll
        for (int kk = 0; kk < 16; kk++) {
            float4 av = *(const float4*)&As[kk][ty * 4];
            float4 bv = *(const float4*)&Bs[kk][tx * 4];
            float a4[4] = {av.x, av.y, av.z, av.w};
            float b4[4] = {bv.x, bv.y, bv.z, bv.w};
#pragma unroll
            for (int i = 0; i < 4; i++)
#pragma unroll
                for (int j = 0; j < 4; j++) acc[i][j] += a4[i] * b4[j];
        }
    }
    float slope = (act == 2) ? aux[0] : 0.f;
#pragma unroll
    for (int i = 0; i < 4; i++) {
        int row = m0 + ty * 4 + i;
        if (row >= M) continue;
#pragma unroll
        for (int j = 0; j < 4; j++) {
            int col = n0 + tx * 4 + j;
            if (col >= N) continue;
            float v = acc[i][j];
            if (bias) v += bias[col];
            if (act == 1) v = fmaxf(v, 0.f);
            else if (act == 2) v = (v >= 0.f) ? v : slope * v;
            C[(size_t)row * N + col] = v;
        }
    }
}

// ---------------- split-K GEMM: part[s] = A_chunk^T @ B_chunk ----------------
// A [Mr,K1] rm, B [Mr,N] rm. chunk s covers rows [s*tiles*16, (s+1)*tiles*16).
__global__ void k_gemm_tn_split(int tiles, int K1, int N,
                                const float* __restrict__ A, const float* __restrict__ B,
                                float* __restrict__ part) {
    __shared__ __align__(16) float As[16][64];
    __shared__ __align__(16) float Bs[16][64];
    int t = threadIdx.x;
    int k0 = blockIdx.x * 64, n0 = blockIdx.y * 64;
    int s = blockIdx.z;
    int mBase = s * tiles * 16;
    int tx = t & 15, ty = t >> 4;
    float acc[4][4];
#pragma unroll
    for (int i = 0; i < 4; i++)
#pragma unroll
        for (int j = 0; j < 4; j++) acc[i][j] = 0.f;
    for (int mt = 0; mt < tiles; mt++) {
        int m0 = mBase + mt * 16;
        __syncthreads();
        for (int idx = t; idx < 1024; idx += 256) {
            int mm = idx >> 6, c = idx & 63;
            As[mm][c] = (k0 + c < K1) ? A[(size_t)(m0 + mm) * K1 + k0 + c] : 0.f;
        }
        for (int idx = t; idx < 1024; idx += 256) {
            int mm = idx >> 6, c = idx & 63;
            Bs[mm][c] = (n0 + c < N) ? B[(size_t)(m0 + mm) * N + n0 + c] : 0.f;
        }
        __syncthreads();
#pragma unroll
        for (int mm = 0; mm < 16; mm++) {
            float4 av = *(const float4*)&As[mm][ty * 4];
            float4 bv = *(const float4*)&Bs[mm][tx * 4];
            float a4[4] = {av.x, av.y, av.z, av.w};
            float b4[4] = {bv.x, bv.y, bv.z, bv.w};
#pragma unroll
            for (int i = 0; i < 4; i++)
#pragma unroll
                for (int j = 0; j < 4; j++) acc[i][j] += a4[i] * b4[j];
        }
    }
#pragma unroll
    for (int i = 0; i < 4; i++) {
        int kr = k0 + ty * 4 + i;
        if (kr >= K1) continue;
#pragma unroll
        for (int j = 0; j < 4; j++) {
            int col = n0 + tx * 4 + j;
            if (col >= N) continue;
            part[((size_t)s * K1 + kr) * N + col] = acc[i][j];
        }
    }
}

__global__ void k_tn_red(const float* __restrict__ part, int S, int K1, int N,
                         const float* __restrict__ divrow, float* __restrict__ out) {
    int i = blockIdx.x * blockDim.x + threadIdx.x;
    if (i >= K1 * N) return;
    float s = 0.f;
    for (int b = 0; b < S; b++) s += part[(size_t)b * K1 * N + i];
    if (divrow) s /= (divrow[i / N] + 1e-12f);
    out[i] = s;
}

// ---------------- tiny colsum for S1 [400 x 20] ----------------
__global__ void k_colsum20(const float* __restrict__ S1, float* __restrict__ cs) {
    int t = threadIdx.x;
    if (t >= C1) return;
    float s = 0.f;
#pragma unroll 4
    for (int r = 0; r < C0; r++) s += S1[r * C1 + t];
    cs[t] = s;
}

// ---------------- tiny stats for xc2 [20 x 128] ----------------
__global__ void k_stats20(const float* __restrict__ A, float* __restrict__ cs,
                          float* __restrict__ css) {
    int f = threadIdx.x;
    float s = 0.f, q = 0.f;
#pragma unroll
    for (int r = 0; r < C1; r++) {
        float v = A[r * FDIM + f];
        s += v; q += v * v;
    }
    cs[f] = s;
    css[f] = q - s * s / (float)C1;
}

// ---------------- tf32 helper ----------------
__device__ __forceinline__ unsigned tf32r(float x) {
    unsigned u;
    asm("cvt.rna.tf32.f32 %0, %1;" : "=r"(u) : "f"(x));
    return u;
}

// ---------------- FUSED: mask(K=400 via tf32 MMA) + mask(K=20 SIMT) + carry ----------------
// CTA: 128 edges. Phase 1: mB[e][f] = sum_k S0[r,k]S0[c,k]G0sq[k,f] via MMA -> smem.
// Phase 2: stage G1sq. Phase 3: thread e computes mA on the fly + sequential carry,
// writes adjs f-major coalesced.
__global__ void __launch_bounds__(256)
k_fused_mask(const float* __restrict__ s0p, const float* __restrict__ g0sq,
             const float* __restrict__ p1, const float* __restrict__ g1sq,
             const int* __restrict__ er, const int* __restrict__ ec,
             const float* __restrict__ adjv, float* __restrict__ outAdj) {
    extern __shared__ __align__(16) char sm[];
    unsigned (*Us)[36]  = (unsigned(*)[36])(sm);             // 18432 B
    unsigned (*Gs)[136] = (unsigned(*)[136])(sm + 18432);    // 17408 B
    float (*Ms)[132]    = (float(*)[132])(sm + 35840);       // 67584 B  [f][e]
    int* rr = (int*)(sm + 103424);
    int* cc = (int*)(sm + 103936);
    float (*G1s)[128]   = (float(*)[128])(sm);               // aliases Us (phase 3)

    int t = threadIdx.x, lane = t & 31, w = t >> 5;
    int e0 = blockIdx.x * 128;
    if (t < 128) { rr[t] = er[e0 + t]; cc[t] = ec[e0 + t]; }
    float acc[16][4];
#pragma unroll
    for (int nt = 0; nt < 16; nt++)
#pragma unroll
        for (int i = 0; i < 4; i++) acc[nt][i] = 0.f;
    __syncthreads();

    for (int k0 = 0; k0 < C0; k0 += 32) {
        for (int idx = t; idx < 32 * 128; idx += 256) {
            int kk = idx >> 7, f = idx & 127;
            float v = (k0 + kk < C0) ? g0sq[(size_t)(k0 + kk) * FDIM + f] : 0.f;
            Gs[kk][f] = tf32r(v);
        }
        for (int idx = t; idx < 128 * 32; idx += 256) {
            int kk = idx & 31, e = idx >> 5;
            float v = 0.f;
            if (k0 + kk < C0)
                v = s0p[(size_t)rr[e] * C0 + k0 + kk] * s0p[(size_t)cc[e] * C0 + k0 + kk];
            Us[e][kk] = tf32r(v);
        }
        __syncthreads();
#pragma unroll
        for (int ks = 0; ks < 4; ks++) {
            int kb = ks * 8;
            int ar = w * 16 + (lane >> 2);
            int ak = kb + (lane & 3);
            unsigned a0 = Us[ar][ak];
            unsigned a1 = Us[ar + 8][ak];
            unsigned a2 = Us[ar][ak + 4];
            unsigned a3 = Us[ar + 8][ak + 4];
#pragma unroll
            for (int nt = 0; nt < 16; nt++) {
                int bn = nt * 8 + (lane >> 2);
                unsigned b0 = Gs[kb + (lane & 3)][bn];
                unsigned b1 = Gs[kb + (lane & 3) + 4][bn];
                asm volatile(
                    "mma.sync.aligned.m16n8k8.row.col.f32.tf32.tf32.f32 "
                    "{%0,%1,%2,%3}, {%4,%5,%6,%7}, {%8,%9}, {%0,%1,%2,%3};"
                    : "+f"(acc[nt][0]), "+f"(acc[nt][1]),
                      "+f"(acc[nt][2]), "+f"(acc[nt][3])
                    : "r"(a0), "r"(a1), "r"(a2), "r"(a3), "r"(b0), "r"(b1));
            }
        }
        __syncthreads();
    }
    // epilogue: acc -> Ms[f][e] (bank-conflict-free)
    {
        int r = w * 16 + (lane >> 2);
        int cb = 2 * (lane & 3);
#pragma unroll
        for (int nt = 0; nt < 16; nt++) {
            int c = nt * 8 + cb;
            Ms[c][r]         = acc[nt][0];
            Ms[c + 1][r]     = acc[nt][1];
            Ms[c][r + 8]     = acc[nt][2];
            Ms[c + 1][r + 8] = acc[nt][3];
        }
    }
    __syncthreads();
    // stage G1sq (aliases Us -- safe after sync)
    for (int idx = t; idx < C1 * FDIM; idx += 256)
        G1s[idx >> 7][idx & 127] = g1sq[idx];
    __syncthreads();
    // carry: thread e
    if (t < 128) {
        int e = t;
        float u20[C1];
        const float* pr = p1 + (size_t)rr[e] * C1;
        const float* pc = p1 + (size_t)cc[e] * C1;
#pragma unroll
        for (int k = 0; k < C1; k++) u20[k] = pr[k] * pc[k];
        float a = adjv[e0 + e];
        for (int f = 0; f < FDIM; f++) {
            float mA = 0.f;
#pragma unroll
            for (int k = 0; k < C1; k++) mA += u20[k] * G1s[k][f];
            float mB = Ms[f][e];
            float tq = a * mA;
            outAdj[(size_t)f * EDGES + e0 + e] = tq + tq * mB;
            a = tq * mB;
        }
    }
}

// ---------------- deterministic CSR build ----------------
__global__ void k_count(const int* __restrict__ er) {
    int e = blockIdx.x * blockDim.x + threadIdx.x;
    if (e < EDGES) atomicAdd(&g_cnt[er[e]], 1);
}

__global__ void k_scan() {
    __shared__ int part[1024];
    const int n = N_NODES;
    const int per = (n + 1023) / 1024;
    int t = threadIdx.x;
    int s = 0;
    int lo = t * per, hi = min(n, (t + 1) * per);
    for (int i = lo; i < hi; i++) s += g_cnt[i];
    part[t] = s; __syncthreads();
    for (int off = 1; off < 1024; off <<= 1) {
        int v = (t >= off) ? part[t - off] : 0;
        __syncthreads();
        part[t] += v;
        __syncthreads();
    }
    int base = (t == 0) ? 0 : part[t - 1];
    for (int i = lo; i < hi; i++) {
        g_off[i] = base; g_cur[i] = base; base += g_cnt[i];
    }
    if (t == 1023) g_off[n] = base;
}

__global__ void k_scatter(const int* __restrict__ er) {
    int e = blockIdx.x * blockDim.x + threadIdx.x;
    if (e < EDGES) {
        int pos = atomicAdd(&g_cur[er[e]], 1);
        g_colS[pos] = e;
    }
}

__global__ void k_rowsort() {
    int r = blockIdx.x * blockDim.x + threadIdx.x;
    if (r >= N_NODES) return;
    int s = g_off[r], e = g_off[r + 1];
    for (int i = s + 1; i < e; i++) {
        int v = g_colS[i];
        int j = i - 1;
        while (j >= s && g_colS[j] > v) { g_colS[j + 1] = g_colS[j]; j--; }
        g_colS[j + 1] = v;
    }
}

__global__ void k_fill(const int* __restrict__ ec, const float* __restrict__ nv) {
    int i = blockIdx.x * blockDim.x + threadIdx.x;
    if (i < EDGES) {
        int e = g_colS[i];
        g_wS[i] = nv[e];
        g_colS[i] = ec[e];
    }
}

// ---------------- one propagation step ----------------
__global__ void k_prop(const float* __restrict__ xin, float* __restrict__ xout) {
    int r = blockIdx.x;
    int f = threadIdx.x;
    float acc = 0.f;
    int s = g_off[r], e = g_off[r + 1];
    for (int i = s; i < e; i++) {
        int c = g_colS[i];
        float w = g_wS[i];
        acc += w * xin[(size_t)c * FDIM + f];
    }
    xout[(size_t)r * FDIM + f] = acc;
}

// ---------------- final logits + log_softmax ----------------
__global__ void k_final(const float* __restrict__ h, const float* __restrict__ W,
                        const float* __restrict__ b, float* __restrict__ out) {
    int warp = (blockIdx.x * blockDim.x + threadIdx.x) >> 5;
    int lane = threadIdx.x & 31;
    if (warp >= N_NODES) return;
    float p0 = 0.f, p1 = 0.f;
#pragma unroll
    for (int j = 0; j < 4; j++) {
        int k = lane + 32 * j;
        float hv = h[(size_t)warp * FDIM + k];
        p0 += hv * W[k * 2];
        p1 += hv * W[k * 2 + 1];
    }
    for (int o = 16; o; o >>= 1) {
        p0 += __shfl_down_sync(0xFFFFFFFFu, p0, o);
        p1 += __shfl_down_sync(0xFFFFFFFFu, p1, o);
    }
    if (lane == 0) {
        float l0 = p0 + b[0], l1 = p1 + b[1];
        float m = fmaxf(l0, l1);
        float ls = m + logf(expf(l0 - m) + expf(l1 - m));
        out[warp * 2]     = l0 - ls;
        out[warp * 2 + 1] = l1 - ls;
    }
}

// ================= host launcher =================
#define GSYM(var, sym) float* var; { void* _p = 0; cudaGetSymbolAddress(&_p, sym); var = (float*)_p; }

extern "C" void kernel_launch(void* const* d_in, const int* in_sizes, int n_in,
                              void* d_out, int out_size) {
    const float* x    = (const float*)d_in[0];
    const float* xcov = (const float*)d_in[1];
    const int*   er   = (const int*)d_in[2];
    const int*   ec   = (const int*)d_in[3];
    const float* adjv = (const float*)d_in[4];
    const float* nv   = (const float*)d_in[5];
    const float* gam  = (const float*)d_in[6];
    const float* bet  = (const float*)d_in[7];
    const float* c0W1 = (const float*)d_in[8];
    const float* c0b1 = (const float*)d_in[9];
    const float* c0W2 = (const float*)d_in[10];
    const float* c0b2 = (const float*)d_in[11];
    const float* c1W1 = (const float*)d_in[12];
    const float* c1b1 = (const float*)d_in[13];
    const float* c1W2 = (const float*)d_in[14];
    const float* c1b2 = (const float*)d_in[15];
    // c2_* (d_in[16..19]) are dead code in the reference
    const float* mW1 = (const float*)d_in[20];
    const float* mb1 = (const float*)d_in[21];
    const float* a1  = (const float*)d_in[22];
    const float* mW2 = (const float*)d_in[23];
    const float* mb2 = (const float*)d_in[24];
    const float* a2  = (const float*)d_in[25];
    const float* mW3 = (const float*)d_in[26];
    const float* mb3 = (const float*)d_in[27];

    float* outLog = (float*)d_out;
    float* outAdj = (float*)d_out + (size_t)N_NODES * 2;

    GSYM(xbn, g_xbn)   GSYM(xp0, g_xp0)   GSYM(xp1, g_xp1)
    GSYM(hA,  g_hA)    GSYM(hB1, g_hB1)   GSYM(hB2, g_hB2)
    GSYM(S0,  g_S0)    GSYM(corr0, g_corr0)
    GSYM(cs0, g_cs0)   GSYM(cs1, g_cs1)
    GSYM(xc1, g_xc1)   GSYM(corr1, g_corr1) GSYM(T0, g_T0) GSYM(G0, g_G0)
    GSYM(S1,  g_S1)    GSYM(xc2, g_xc2)   GSYM(corr2, g_corr2)
    GSYM(T1,  g_T1)    GSYM(G1,  g_G1)    GSYM(P1,  g_P1)
    GSYM(pa1, g_pa1)   GSYM(pa2, g_pa2)
    GSYM(csA, g_csA)   GSYM(cssA, g_cssA)
    GSYM(csB, g_csB)   GSYM(cssB, g_cssB)
    GSYM(csC, g_csC)   GSYM(cssC, g_cssC)
    GSYM(pb1, g_pb1)   GSYM(pb2, g_pb2)
    GSYM(csX, g_csX)   GSYM(cssX, g_cssX)
    GSYM(tnp, g_tnpart)
    void* cntp = 0; cudaGetSymbolAddress(&cntp, g_cnt);

    static_assert(sizeof(float) == 4, "");
    const int FUSED_SMEM = 104448;
    cudaFuncSetAttribute(k_fused_mask, cudaFuncAttributeMaxDynamicSharedMemorySize,
                         FUSED_SMEM);

    // fork a second stream for the independent BN/CSR/prop/MLP chain
    cudaStream_t s2;
    cudaStreamCreateWithFlags(&s2, cudaStreamNonBlocking);
    cudaEvent_t evFork, evJoin;
    cudaEventCreateWithFlags(&evFork, cudaEventDisableTiming);
    cudaEventCreateWithFlags(&evJoin, cudaEventDisableTiming);
    cudaEventRecord(evFork, 0);
    cudaStreamWaitEvent(s2, evFork, 0);

    // ================= chain B (stream s2): bn -> CSR -> prop -> MLP -> outLog ====
    k_psum<<<250, 128, 0, s2>>>(x, N_NODES, FDIM, 32, pb1, pb2);
    k_preduce<<<1, 128, 0, s2>>>(pb1, pb2, 250, FDIM, N_NODES, csX, cssX);
    k_bn<<<(N_NODES * FDIM + 255) / 256, 256, 0, s2>>>(x, csX, cssX, gam, bet, xbn);

    cudaMemsetAsync(cntp, 0, N_NODES * 4, s2);
    k_count<<<EDGES / 256, 256, 0, s2>>>(er);
    k_scan<<<1, 1024, 0, s2>>>();
    k_scatter<<<EDGES / 256, 256, 0, s2>>>(er);
    k_rowsort<<<(N_NODES + 127) / 128, 128, 0, s2>>>();
    k_fill<<<EDGES / 256, 256, 0, s2>>>(ec, nv);

    {
        const float* cur = xbn;
        float* bufs[2] = {xp0, xp1};
        for (int it = 0; it < 10; it++) {
            float* o = bufs[it & 1];
            k_prop<<<N_NODES, 128, 0, s2>>>(cur, o);
            cur = o;
        }
        // cur == xp1 after 10 steps
    }
    k_gemm_nn<<<dim3(125, 2), 256, 0, s2>>>(N_NODES, FDIM, FDIM, xp1, mW1, mb1, hB1, 2, a1);
    k_gemm_nn<<<dim3(125, 2), 256, 0, s2>>>(N_NODES, FDIM, FDIM, hB1, mW2, mb2, hB2, 2, a2);
    k_final<<<(N_NODES * 32 + 255) / 256, 256, 0, s2>>>(hB2, mW3, mb3, outLog);

    // ================= chain A (stream 0): clustering -> masks -> outAdj =========
    // corr0 = node_corr(x_cov)
    k_psum<<<250, 128>>>(xcov, N_NODES, FDIM, 32, pa1, pa2);
    k_preduce<<<1, 128>>>(pa1, pa2, 250, FDIM, N_NODES, csA, cssA);
    k_corr<<<N_NODES, 128>>>(xcov, N_NODES, csA, cssA, corr0);

    // level 0 cluster
    k_gemm_nn<<<dim3(125, 2), 256>>>(N_NODES, FDIM, FDIM, xcov, c0W1, c0b1, hA, 1, 0);
    k_gemm_nn<<<dim3(125, 7), 256>>>(N_NODES, C0, FDIM, hA, c0W2, c0b2, S0, 0, 0);
    k_softmax<<<N_NODES, 128>>>(S0, C0);
    k_psum<<<250, 128>>>(S0, N_NODES, C0, 32, pa1, 0);
    k_preduce<<<4, 128>>>(pa1, 0, 250, C0, N_NODES, cs0, 0);
    // xc1 = (S0^T @ xcov) / cs0 ; T0 = S0^T @ corr0   (split-K, S=20 x 400 rows)
    k_gemm_tn_split<<<dim3(7, 2, 20), 256>>>(25, C0, FDIM, S0, xcov, tnp);
    k_tn_red<<<(C0 * FDIM + 255) / 256, 256>>>(tnp, 20, C0, FDIM, cs0, xc1);
    k_gemm_tn_split<<<dim3(7, 2, 20), 256>>>(25, C0, FDIM, S0, corr0, tnp);
    k_tn_red<<<(C0 * FDIM + 255) / 256, 256>>>(tnp, 20, C0, FDIM, 0, T0);

    // corr1, gains0
    k_psum<<<16, 128>>>(xc1, C0, FDIM, 25, pa1, pa2);
    k_preduce<<<1, 128>>>(pa1, pa2, 16, FDIM, C0, csB, cssB);
    k_corr<<<C0, 128>>>(xc1, C0, csB, cssB, corr1);
    k_gains<<<(C0 * FDIM + 255) / 256, 256>>>(corr1, T0, G0, C0 * FDIM);

    // level 1 cluster
    k_gemm_nn<<<dim3(7, 2), 256>>>(C0, FDIM, FDIM, xc1, c1W1, c1b1, hA, 1, 0);
    k_gemm_nn<<<dim3(7, 1), 256>>>(C0, C1, FDIM, hA, c1W2, c1b2, S1, 0, 0);
    k_softmax<<<C0, 32>>>(S1, C1);
    k_colsum20<<<1, 32>>>(S1, cs1);
    k_gemm_tn_split<<<dim3(1, 2, 5), 256>>>(5, C1, FDIM, S1, xc1, tnp);
    k_tn_red<<<(C1 * FDIM + 255) / 256, 256>>>(tnp, 5, C1, FDIM, cs1, xc2);
    k_gemm_tn_split<<<dim3(1, 2, 5), 256>>>(5, C1, FDIM, S1, corr1, tnp);
    k_tn_red<<<(C1 * FDIM + 255) / 256, 256>>>(tnp, 5, C1, FDIM, 0, T1);

    // corr2, gains1
    k_stats20<<<1, 128>>>(xc2, csC, cssC);
    k_corr<<<C1, 128>>>(xc2, C1, csC, cssC, corr2);
    k_gains<<<(C1 * FDIM + 255) / 256, 256>>>(corr2, T1, G1, C1 * FDIM);

    // projector P1 = S0 @ S1
    k_gemm_nn<<<dim3(125, 1), 256>>>(N_NODES, C1, C0, S0, S1, 0, P1, 0, 0);

    // fused masks + carry -> adjs output
    k_fused_mask<<<EDGES / 128, 256, FUSED_SMEM>>>(S0, G0, P1, G1, er, ec, adjv, outAdj);

    // ================= join =================
    cudaEventRecord(evJoin, s2);
    cudaStreamWaitEvent(0, evJoin, 0);

    cudaEventDestroy(evFork);
    cudaEventDestroy(evJoin);
    cudaStreamDestroy(s2);

    (void)in_sizes; (void)n_in; (void)out_size;
}